// round 2
// baseline (speedup 1.0000x reference)
#include <cuda_runtime.h>
#include <math.h>

#define TT 4096
#define II 512
#define HH 1024
#define OO 256

#define REC_GRID 128
#define REC_THREADS 256   // 8 warps; warp w owns hidden unit blockIdx.x*8+w
#define UNITS_PER_CTA 8

// Scratch (allocation-free: __device__ globals)
__device__ float g_gx[4][TT][HH];        // per-gate input projections
__device__ float g_h[(TT + 1) * HH];     // row 0 = h_{-1} = 0, row t+1 = h_t
__device__ unsigned g_flag[REC_GRID];    // per-CTA step flags (monotonic per launch)

// ---------------------------------------------------------------------------
// init: zero h row 0 and the flags (must run every launch -> graph-safe)
// ---------------------------------------------------------------------------
__global__ void init_kernel() {
    int i = blockIdx.x * blockDim.x + threadIdx.x;
    if (i < HH) g_h[i] = 0.0f;
    if (i < REC_GRID) g_flag[i] = 0u;
}

// ---------------------------------------------------------------------------
// C[M,N] = A[M,K] @ B[N,K]^T + bias[N]   (both A and B are K-contiguous)
// 64x64 tile, BK=16, 256 threads, 4x4 microtile per thread.
// ---------------------------------------------------------------------------
__global__ __launch_bounds__(256) void gemm_tn_bias(
    const float* __restrict__ A, const float* __restrict__ B,
    const float* __restrict__ bias, float* __restrict__ C,
    int M, int N, int K)
{
    __shared__ float As[16][68];  // [BK][BM+4] pad keeps float4 rows 16B aligned
    __shared__ float Bs[16][68];

    const int bm = blockIdx.y * 64;
    const int bn = blockIdx.x * 64;
    const int tid = threadIdx.x;

    const int lr = tid >> 2;          // 0..63 : tile row for gmem load
    const int lk = (tid & 3) << 2;    // 0,4,8,12 : k offset for gmem load
    const int tx = tid & 15;          // 0..15 : n micro
    const int ty = tid >> 4;          // 0..15 : m micro

    float acc[4][4] = {};

    for (int k0 = 0; k0 < K; k0 += 16) {
        float4 av = *(const float4*)(A + (size_t)(bm + lr) * K + k0 + lk);
        float4 bv = *(const float4*)(B + (size_t)(bn + lr) * K + k0 + lk);
        __syncthreads();
        As[lk + 0][lr] = av.x; As[lk + 1][lr] = av.y;
        As[lk + 2][lr] = av.z; As[lk + 3][lr] = av.w;
        Bs[lk + 0][lr] = bv.x; Bs[lk + 1][lr] = bv.y;
        Bs[lk + 2][lr] = bv.z; Bs[lk + 3][lr] = bv.w;
        __syncthreads();
#pragma unroll
        for (int kk = 0; kk < 16; kk++) {
            float4 af = *(const float4*)&As[kk][ty * 4];
            float4 bf = *(const float4*)&Bs[kk][tx * 4];
            float am[4] = {af.x, af.y, af.z, af.w};
            float bn_[4] = {bf.x, bf.y, bf.z, bf.w};
#pragma unroll
            for (int i = 0; i < 4; i++)
#pragma unroll
                for (int j = 0; j < 4; j++)
                    acc[i][j] += am[i] * bn_[j];
        }
    }

    const int row = bm + ty * 4;
    const int col = bn + tx * 4;
    float b0 = bias[col + 0], b1 = bias[col + 1], b2 = bias[col + 2], b3 = bias[col + 3];
#pragma unroll
    for (int i = 0; i < 4; i++) {
        float4 out;
        out.x = acc[i][0] + b0;
        out.y = acc[i][1] + b1;
        out.z = acc[i][2] + b2;
        out.w = acc[i][3] + b3;
        *(float4*)&C[(size_t)(row + i) * N + col] = out;
    }
}

// ---------------------------------------------------------------------------
// Persistent recurrence kernel. 128 CTAs resident, 8 warps each.
// Warp w of CTA b owns hidden unit u = b*8+w: all 4 gate rows of Wh live in
// that warp's registers. c_u lives in lane-0 regs.
// Synchronization: per-CTA release flags (st.release.gpu) + 128-wide acquire
// spin — no single-address atomic serialization.
// ---------------------------------------------------------------------------
__global__ __launch_bounds__(REC_THREADS, 1) void lstm_rec(
    const float* __restrict__ Whf, const float* __restrict__ Whi,
    const float* __restrict__ Whc, const float* __restrict__ Who)
{
    const int w = threadIdx.x >> 5;
    const int l = threadIdx.x & 31;
    const int unit = blockIdx.x * UNITS_PER_CTA + w;

    // Load recurrent weights into registers (once), float4-interleaved:
    // lane l, chunk i covers h indices [l*4 + 128*i, +4)
    float4 wf[8], wi[8], wc[8], wo[8];
    {
        const float* rf = Whf + (size_t)unit * HH;
        const float* ri = Whi + (size_t)unit * HH;
        const float* rc = Whc + (size_t)unit * HH;
        const float* ro = Who + (size_t)unit * HH;
#pragma unroll
        for (int i = 0; i < 8; i++) {
            int c = l * 4 + 128 * i;
            wf[i] = *(const float4*)(rf + c);
            wi[i] = *(const float4*)(ri + c);
            wc[i] = *(const float4*)(rc + c);
            wo[i] = *(const float4*)(ro + c);
        }
    }

    float cst = 0.0f;  // cell state for this unit (meaningful in lane 0)

    const unsigned* myflag = (threadIdx.x < REC_GRID) ? &g_flag[threadIdx.x] : &g_flag[0];

    for (int t = 0; t < TT; t++) {
        // ---- prefetch gx for this step (latency hides under spin + dot) ----
        float gxf = 0.f, gxi = 0.f, gxc = 0.f, gxo = 0.f;
        if (l == 0) {
            gxf = __ldcg(&g_gx[0][t][unit]);
            gxi = __ldcg(&g_gx[1][t][unit]);
            gxc = __ldcg(&g_gx[2][t][unit]);
            gxo = __ldcg(&g_gx[3][t][unit]);
        }

        // ---- barrier acquire: wait until every CTA published step t ----
        if (threadIdx.x < REC_GRID) {
            unsigned v;
            do {
                asm volatile("ld.acquire.gpu.global.u32 %0, [%1];"
                             : "=r"(v) : "l"(myflag) : "memory");
            } while ((int)v < t);
        }
        __syncthreads();

        const float* hrow = g_h + (size_t)t * HH;

        float af = 0.f, ai = 0.f, ac = 0.f, ao = 0.f;
#pragma unroll
        for (int i = 0; i < 8; i++) {
            float4 hv = __ldcg((const float4*)(hrow + l * 4 + 128 * i));
            af += wf[i].x * hv.x; ai += wi[i].x * hv.x; ac += wc[i].x * hv.x; ao += wo[i].x * hv.x;
            af += wf[i].y * hv.y; ai += wi[i].y * hv.y; ac += wc[i].y * hv.y; ao += wo[i].y * hv.y;
            af += wf[i].z * hv.z; ai += wi[i].z * hv.z; ac += wc[i].z * hv.z; ao += wo[i].z * hv.z;
            af += wf[i].w * hv.w; ai += wi[i].w * hv.w; ac += wc[i].w * hv.w; ao += wo[i].w * hv.w;
        }
#pragma unroll
        for (int off = 16; off > 0; off >>= 1) {
            af += __shfl_xor_sync(0xffffffffu, af, off);
            ai += __shfl_xor_sync(0xffffffffu, ai, off);
            ac += __shfl_xor_sync(0xffffffffu, ac, off);
            ao += __shfl_xor_sync(0xffffffffu, ao, off);
        }

        if (l == 0) {
            float gf = af + gxf;
            float gi = ai + gxi;
            float gc = ac + gxc;
            float go = ao + gxo;
            float f_ = 1.0f / (1.0f + __expf(-gf));
            float i_ = 1.0f / (1.0f + __expf(-gi));
            float cd = __tanhf(gc);
            float o_ = 1.0f / (1.0f + __expf(-go));
            cst = f_ * cst + i_ * cd;
            float h_ = o_ * cst;                   // reference omits tanh(c)
            __stcg(&g_h[(size_t)(t + 1) * HH + unit], h_);
        }

        // ---- release: publish our 8 h values for step t+1 ----
        __syncthreads();
        if (threadIdx.x == 0) {
            unsigned nv = (unsigned)(t + 1);
            asm volatile("st.release.gpu.global.u32 [%0], %1;"
                         :: "l"(&g_flag[blockIdx.x]), "r"(nv) : "memory");
        }
    }
}

// ---------------------------------------------------------------------------
extern "C" void kernel_launch(void* const* d_in, const int* in_sizes, int n_in,
                              void* d_out, int out_size)
{
    const float* x   = (const float*)d_in[0];
    const float* Wxf = (const float*)d_in[1];
    const float* Whf = (const float*)d_in[2];
    const float* bf  = (const float*)d_in[3];
    const float* Wxi = (const float*)d_in[4];
    const float* Whi = (const float*)d_in[5];
    const float* bi  = (const float*)d_in[6];
    const float* Wxc = (const float*)d_in[7];
    const float* Whc = (const float*)d_in[8];
    const float* bc  = (const float*)d_in[9];
    const float* Wxo = (const float*)d_in[10];
    const float* Who = (const float*)d_in[11];
    const float* bo  = (const float*)d_in[12];
    const float* Wy  = (const float*)d_in[13];
    const float* by  = (const float*)d_in[14];
    float* y = (float*)d_out;

    void* p_gx = nullptr;
    void* p_h  = nullptr;
    cudaGetSymbolAddress(&p_gx, g_gx);
    cudaGetSymbolAddress(&p_h,  g_h);
    float* gx = (float*)p_gx;
    float* hbuf = (float*)p_h;

    init_kernel<<<4, 256>>>();

    // Input projections: 4 GEMMs [4096,1024] = x[4096,512] @ Wx^T + b
    dim3 g1(HH / 64, TT / 64);
    gemm_tn_bias<<<g1, 256>>>(x, Wxf, bf, gx + 0 * (size_t)TT * HH, TT, HH, II);
    gemm_tn_bias<<<g1, 256>>>(x, Wxi, bi, gx + 1 * (size_t)TT * HH, TT, HH, II);
    gemm_tn_bias<<<g1, 256>>>(x, Wxc, bc, gx + 2 * (size_t)TT * HH, TT, HH, II);
    gemm_tn_bias<<<g1, 256>>>(x, Wxo, bo, gx + 3 * (size_t)TT * HH, TT, HH, II);

    // Sequential recurrence (persistent, weights in registers)
    lstm_rec<<<REC_GRID, REC_THREADS>>>(Whf, Whi, Whc, Who);

    // Output projection: y[4096,256] = hs[4096,1024] @ Wy^T + by
    dim3 g2(OO / 64, TT / 64);
    gemm_tn_bias<<<g2, 256>>>(hbuf + HH, Wy, by, y, TT, OO, HH);
}

// round 3
// speedup vs baseline: 1.2105x; 1.2105x over previous
#include <cuda_runtime.h>
#include <math.h>

#define TT 4096
#define II 512
#define HH 1024
#define OO 256

#define REC_GRID 128
#define REC_THREADS 256   // 8 warps; warp w owns hidden unit blockIdx.x*8+w
#define UNITS_PER_CTA 8

// Scratch (allocation-free: __device__ globals)
__device__ float g_gx[4][TT][HH];        // per-gate input projections
__device__ float g_h[(TT + 1) * HH];     // row 0 = h_{-1} = 0, row t+1 = h_t
__device__ unsigned g_flag[REC_GRID];    // per-CTA arrival flags (monotonic per launch)
__device__ unsigned g_gen[32];           // g_gen[0] = broadcast generation (own line)

// ---------------------------------------------------------------------------
// init: zero h row 0, flags, generation (runs every launch -> graph-safe)
// ---------------------------------------------------------------------------
__global__ void init_kernel() {
    int i = blockIdx.x * blockDim.x + threadIdx.x;
    if (i < HH) g_h[i] = 0.0f;
    if (i < REC_GRID) g_flag[i] = 0u;
    if (i < 32) g_gen[i] = 0u;
}

// ---------------------------------------------------------------------------
// C[M,N] = A[M,K] @ B[N,K]^T + bias[N]   (both A and B are K-contiguous)
// 64x64 tile, BK=16, 256 threads, 4x4 microtile per thread.
// ---------------------------------------------------------------------------
__global__ __launch_bounds__(256) void gemm_tn_bias(
    const float* __restrict__ A, const float* __restrict__ B,
    const float* __restrict__ bias, float* __restrict__ C,
    int M, int N, int K)
{
    __shared__ float As[16][68];
    __shared__ float Bs[16][68];

    const int bm = blockIdx.y * 64;
    const int bn = blockIdx.x * 64;
    const int tid = threadIdx.x;

    const int lr = tid >> 2;
    const int lk = (tid & 3) << 2;
    const int tx = tid & 15;
    const int ty = tid >> 4;

    float acc[4][4] = {};

    for (int k0 = 0; k0 < K; k0 += 16) {
        float4 av = *(const float4*)(A + (size_t)(bm + lr) * K + k0 + lk);
        float4 bv = *(const float4*)(B + (size_t)(bn + lr) * K + k0 + lk);
        __syncthreads();
        As[lk + 0][lr] = av.x; As[lk + 1][lr] = av.y;
        As[lk + 2][lr] = av.z; As[lk + 3][lr] = av.w;
        Bs[lk + 0][lr] = bv.x; Bs[lk + 1][lr] = bv.y;
        Bs[lk + 2][lr] = bv.z; Bs[lk + 3][lr] = bv.w;
        __syncthreads();
#pragma unroll
        for (int kk = 0; kk < 16; kk++) {
            float4 af = *(const float4*)&As[kk][ty * 4];
            float4 bf = *(const float4*)&Bs[kk][tx * 4];
            float am[4] = {af.x, af.y, af.z, af.w};
            float bn_[4] = {bf.x, bf.y, bf.z, bf.w};
#pragma unroll
            for (int i = 0; i < 4; i++)
#pragma unroll
                for (int j = 0; j < 4; j++)
                    acc[i][j] += am[i] * bn_[j];
        }
    }

    const int row = bm + ty * 4;
    const int col = bn + tx * 4;
    float b0 = bias[col + 0], b1 = bias[col + 1], b2 = bias[col + 2], b3 = bias[col + 3];
#pragma unroll
    for (int i = 0; i < 4; i++) {
        float4 out;
        out.x = acc[i][0] + b0;
        out.y = acc[i][1] + b1;
        out.z = acc[i][2] + b2;
        out.w = acc[i][3] + b3;
        *(float4*)&C[(size_t)(row + i) * N + col] = out;
    }
}

// ---------------------------------------------------------------------------
// Persistent recurrence kernel. 128 CTAs resident, 8 warps each.
// Warp w of CTA b owns hidden unit u = b*8+w (all 4 gate rows in registers).
// Barrier: per-CTA release flags -> CTA0 warp0 gathers -> release generation
// -> 127 scalar pollers. Minimal L2 poll traffic on the publish path.
// ---------------------------------------------------------------------------
__global__ __launch_bounds__(REC_THREADS, 1) void lstm_rec(
    const float* __restrict__ Whf, const float* __restrict__ Whi,
    const float* __restrict__ Whc, const float* __restrict__ Who)
{
    const int w = threadIdx.x >> 5;
    const int l = threadIdx.x & 31;
    const int unit = blockIdx.x * UNITS_PER_CTA + w;

    // Recurrent weights into registers (once). Lane l chunk i: h[l*4+128*i ..+4)
    float4 wf[8], wi[8], wc[8], wo[8];
    {
        const float* rf = Whf + (size_t)unit * HH;
        const float* ri = Whi + (size_t)unit * HH;
        const float* rc = Whc + (size_t)unit * HH;
        const float* ro = Who + (size_t)unit * HH;
#pragma unroll
        for (int i = 0; i < 8; i++) {
            int c = l * 4 + 128 * i;
            wf[i] = *(const float4*)(rf + c);
            wi[i] = *(const float4*)(ri + c);
            wc[i] = *(const float4*)(rc + c);
            wo[i] = *(const float4*)(ro + c);
        }
    }

    float cst = 0.0f;  // cell state (lane 0)

    for (int t = 0; t < TT; t++) {
        // ---- prefetch gx (latency hides under barrier wait) ----
        float gxf = 0.f, gxi = 0.f, gxc = 0.f, gxo = 0.f;
        if (l == 0) {
            gxf = __ldcg(&g_gx[0][t][unit]);
            gxi = __ldcg(&g_gx[1][t][unit]);
            gxc = __ldcg(&g_gx[2][t][unit]);
            gxo = __ldcg(&g_gx[3][t][unit]);
        }

        // ---- barrier wait: h row t must be fully published ----
        if (blockIdx.x == 0) {
            if (threadIdx.x < 32) {
                // gather: lane polls 4 flags
#pragma unroll
                for (int j = 0; j < 4; j++) {
                    const unsigned* p = &g_flag[threadIdx.x + 32 * j];
                    unsigned v;
                    do {
                        asm volatile("ld.acquire.gpu.global.u32 %0, [%1];"
                                     : "=r"(v) : "l"(p) : "memory");
                    } while (v < (unsigned)t);
                }
                __syncwarp();
                if (threadIdx.x == 0) {
                    asm volatile("st.release.gpu.global.u32 [%0], %1;"
                                 :: "l"(&g_gen[0]), "r"((unsigned)t) : "memory");
                }
            }
        } else {
            if (threadIdx.x == 0) {
                unsigned v;
                do {
                    asm volatile("ld.acquire.gpu.global.u32 %0, [%1];"
                                 : "=r"(v) : "l"(&g_gen[0]) : "memory");
                } while (v < (unsigned)t);
            }
        }
        __syncthreads();

        const float* hrow = g_h + (size_t)t * HH;

        float af = 0.f, ai = 0.f, ac = 0.f, ao = 0.f;
#pragma unroll
        for (int i = 0; i < 8; i++) {
            float4 hv = __ldcg((const float4*)(hrow + l * 4 + 128 * i));
            af += wf[i].x * hv.x; ai += wi[i].x * hv.x; ac += wc[i].x * hv.x; ao += wo[i].x * hv.x;
            af += wf[i].y * hv.y; ai += wi[i].y * hv.y; ac += wc[i].y * hv.y; ao += wo[i].y * hv.y;
            af += wf[i].z * hv.z; ai += wi[i].z * hv.z; ac += wc[i].z * hv.z; ao += wo[i].z * hv.z;
            af += wf[i].w * hv.w; ai += wi[i].w * hv.w; ac += wc[i].w * hv.w; ao += wo[i].w * hv.w;
        }
#pragma unroll
        for (int off = 16; off > 0; off >>= 1) {
            af += __shfl_xor_sync(0xffffffffu, af, off);
            ai += __shfl_xor_sync(0xffffffffu, ai, off);
            ac += __shfl_xor_sync(0xffffffffu, ac, off);
            ao += __shfl_xor_sync(0xffffffffu, ao, off);
        }

        if (l == 0) {
            float gf = af + gxf;
            float gi = ai + gxi;
            float gc = ac + gxc;
            float go = ao + gxo;
            float f_ = 1.0f / (1.0f + __expf(-gf));
            float i_ = 1.0f / (1.0f + __expf(-gi));
            float cd = __tanhf(gc);
            float o_ = 1.0f / (1.0f + __expf(-go));
            cst = f_ * cst + i_ * cd;
            float h_ = o_ * cst;                   // reference omits tanh(c)
            __stcg(&g_h[(size_t)(t + 1) * HH + unit], h_);
        }

        // ---- arrival: publish our 8 h values for step t+1 ----
        __syncthreads();
        if (threadIdx.x == 0) {
            asm volatile("st.release.gpu.global.u32 [%0], %1;"
                         :: "l"(&g_flag[blockIdx.x]), "r"((unsigned)(t + 1)) : "memory");
        }
    }
}

// ---------------------------------------------------------------------------
extern "C" void kernel_launch(void* const* d_in, const int* in_sizes, int n_in,
                              void* d_out, int out_size)
{
    const float* x   = (const float*)d_in[0];
    const float* Wxf = (const float*)d_in[1];
    const float* Whf = (const float*)d_in[2];
    const float* bf  = (const float*)d_in[3];
    const float* Wxi = (const float*)d_in[4];
    const float* Whi = (const float*)d_in[5];
    const float* bi  = (const float*)d_in[6];
    const float* Wxc = (const float*)d_in[7];
    const float* Whc = (const float*)d_in[8];
    const float* bc  = (const float*)d_in[9];
    const float* Wxo = (const float*)d_in[10];
    const float* Who = (const float*)d_in[11];
    const float* bo  = (const float*)d_in[12];
    const float* Wy  = (const float*)d_in[13];
    const float* by  = (const float*)d_in[14];
    float* y = (float*)d_out;

    void* p_gx = nullptr;
    void* p_h  = nullptr;
    cudaGetSymbolAddress(&p_gx, g_gx);
    cudaGetSymbolAddress(&p_h,  g_h);
    float* gx = (float*)p_gx;
    float* hbuf = (float*)p_h;

    init_kernel<<<4, 256>>>();

    // Input projections: 4 GEMMs [4096,1024] = x[4096,512] @ Wx^T + b
    dim3 g1(HH / 64, TT / 64);
    gemm_tn_bias<<<g1, 256>>>(x, Wxf, bf, gx + 0 * (size_t)TT * HH, TT, HH, II);
    gemm_tn_bias<<<g1, 256>>>(x, Wxi, bi, gx + 1 * (size_t)TT * HH, TT, HH, II);
    gemm_tn_bias<<<g1, 256>>>(x, Wxc, bc, gx + 2 * (size_t)TT * HH, TT, HH, II);
    gemm_tn_bias<<<g1, 256>>>(x, Wxo, bo, gx + 3 * (size_t)TT * HH, TT, HH, II);

    // Sequential recurrence (persistent, weights in registers)
    lstm_rec<<<REC_GRID, REC_THREADS>>>(Whf, Whi, Whc, Who);

    // Output projection: y[4096,256] = hs[4096,1024] @ Wy^T + by
    dim3 g2(OO / 64, TT / 64);
    gemm_tn_bias<<<g2, 256>>>(hbuf + HH, Wy, by, y, TT, OO, HH);
}

// round 5
// speedup vs baseline: 2.3065x; 1.9053x over previous
#include <cuda_runtime.h>
#include <math.h>

#define TT 4096
#define II 512
#define HH 1024
#define OO 256

#define REC_GRID 128
#define REC_THREADS 256   // 8 warps; warp w owns hidden unit blockIdx.x*8+w
#define UNITS_PER_CTA 8

// Scratch (allocation-free: __device__ globals)
__device__ float g_gx[4][TT][HH];        // per-gate input projections
__device__ float g_h[(TT + 1) * HH];     // row 0 = h_{-1} = 0, row t+1 = h_t
__device__ unsigned g_bar;               // grid barrier counter (monotonic per launch)

// ---------------------------------------------------------------------------
// init: zero h row 0 and the barrier counter (runs every launch -> graph-safe)
// ---------------------------------------------------------------------------
__global__ void init_kernel() {
    int i = blockIdx.x * blockDim.x + threadIdx.x;
    if (i < HH) g_h[i] = 0.0f;
    if (i == 0) g_bar = 0u;
}

// ---------------------------------------------------------------------------
// C[M,N] = A[M,K] @ B[N,K]^T + bias[N]   (both A and B are K-contiguous)
// ---------------------------------------------------------------------------
__global__ __launch_bounds__(256) void gemm_tn_bias(
    const float* __restrict__ A, const float* __restrict__ B,
    const float* __restrict__ bias, float* __restrict__ C,
    int M, int N, int K)
{
    __shared__ float As[16][68];
    __shared__ float Bs[16][68];

    const int bm = blockIdx.y * 64;
    const int bn = blockIdx.x * 64;
    const int tid = threadIdx.x;

    const int lr = tid >> 2;
    const int lk = (tid & 3) << 2;
    const int tx = tid & 15;
    const int ty = tid >> 4;

    float acc[4][4] = {};

    for (int k0 = 0; k0 < K; k0 += 16) {
        float4 av = *(const float4*)(A + (size_t)(bm + lr) * K + k0 + lk);
        float4 bv = *(const float4*)(B + (size_t)(bn + lr) * K + k0 + lk);
        __syncthreads();
        As[lk + 0][lr] = av.x; As[lk + 1][lr] = av.y;
        As[lk + 2][lr] = av.z; As[lk + 3][lr] = av.w;
        Bs[lk + 0][lr] = bv.x; Bs[lk + 1][lr] = bv.y;
        Bs[lk + 2][lr] = bv.z; Bs[lk + 3][lr] = bv.w;
        __syncthreads();
#pragma unroll
        for (int kk = 0; kk < 16; kk++) {
            float4 af = *(const float4*)&As[kk][ty * 4];
            float4 bf = *(const float4*)&Bs[kk][tx * 4];
            float am[4] = {af.x, af.y, af.z, af.w};
            float bn_[4] = {bf.x, bf.y, bf.z, bf.w};
#pragma unroll
            for (int i = 0; i < 4; i++)
#pragma unroll
                for (int j = 0; j < 4; j++)
                    acc[i][j] += am[i] * bn_[j];
        }
    }

    const int row = bm + ty * 4;
    const int col = bn + tx * 4;
    float b0 = bias[col + 0], b1 = bias[col + 1], b2 = bias[col + 2], b3 = bias[col + 3];
#pragma unroll
    for (int i = 0; i < 4; i++) {
        float4 out;
        out.x = acc[i][0] + b0;
        out.y = acc[i][1] + b1;
        out.z = acc[i][2] + b2;
        out.w = acc[i][3] + b3;
        *(float4*)&C[(size_t)(row + i) * N + col] = out;
    }
}

__device__ __forceinline__ float fast_sigmoid(float x) {
    return 0.5f * __tanhf(0.5f * x) + 0.5f;   // one MUFU, no divide
}

// ---------------------------------------------------------------------------
// Persistent recurrence kernel. 128 CTAs resident, 8 warps each.
// Warp w of CTA b owns hidden unit u = b*8+w (all 4 gate rows in registers).
// Barrier: round-1 proven mechanism (single atomic counter, thread-0 poll),
// but the gpu-scope fence is executed by thread 0 only (cta-scope
// happens-before via __syncthreads makes it cumulative — CG grid.sync pattern).
// gx loads are software-pipelined one step ahead to hide DRAM latency.
// ---------------------------------------------------------------------------
__global__ __launch_bounds__(REC_THREADS, 1) void lstm_rec(
    const float* __restrict__ Whf, const float* __restrict__ Whi,
    const float* __restrict__ Whc, const float* __restrict__ Who)
{
    const int w = threadIdx.x >> 5;
    const int l = threadIdx.x & 31;
    const int unit = blockIdx.x * UNITS_PER_CTA + w;

    // Recurrent weights into registers (once). Lane l chunk i: h[l*4+128*i ..+4)
    float4 wf[8], wi[8], wc[8], wo[8];
    {
        const float* rf = Whf + (size_t)unit * HH;
        const float* ri = Whi + (size_t)unit * HH;
        const float* rc = Whc + (size_t)unit * HH;
        const float* ro = Who + (size_t)unit * HH;
#pragma unroll
        for (int i = 0; i < 8; i++) {
            int c = l * 4 + 128 * i;
            wf[i] = *(const float4*)(rf + c);
            wi[i] = *(const float4*)(ri + c);
            wc[i] = *(const float4*)(rc + c);
            wo[i] = *(const float4*)(ro + c);
        }
    }

    float cst = 0.0f;  // cell state (lane 0)

    // Prefetch gx for t=0
    float gxf = 0.f, gxi = 0.f, gxc = 0.f, gxo = 0.f;
    if (l == 0) {
        gxf = __ldcg(&g_gx[0][0][unit]);
        gxi = __ldcg(&g_gx[1][0][unit]);
        gxc = __ldcg(&g_gx[2][0][unit]);
        gxo = __ldcg(&g_gx[3][0][unit]);
    }

    for (int t = 0; t < TT; t++) {
        const float* hrow = g_h + (size_t)t * HH;

        float af = 0.f, ai = 0.f, ac = 0.f, ao = 0.f;
#pragma unroll
        for (int i = 0; i < 8; i++) {
            float4 hv = __ldcg((const float4*)(hrow + l * 4 + 128 * i));
            af += wf[i].x * hv.x; ai += wi[i].x * hv.x; ac += wc[i].x * hv.x; ao += wo[i].x * hv.x;
            af += wf[i].y * hv.y; ai += wi[i].y * hv.y; ac += wc[i].y * hv.y; ao += wo[i].y * hv.y;
            af += wf[i].z * hv.z; ai += wi[i].z * hv.z; ac += wc[i].z * hv.z; ao += wo[i].z * hv.z;
            af += wf[i].w * hv.w; ai += wi[i].w * hv.w; ac += wc[i].w * hv.w; ao += wo[i].w * hv.w;
        }
#pragma unroll
        for (int off = 16; off > 0; off >>= 1) {
            af += __shfl_xor_sync(0xffffffffu, af, off);
            ai += __shfl_xor_sync(0xffffffffu, ai, off);
            ac += __shfl_xor_sync(0xffffffffu, ac, off);
            ao += __shfl_xor_sync(0xffffffffu, ao, off);
        }

        if (l == 0) {
            float f_ = fast_sigmoid(af + gxf);
            float i_ = fast_sigmoid(ai + gxi);
            float cd = __tanhf(ac + gxc);
            float o_ = fast_sigmoid(ao + gxo);
            cst = f_ * cst + i_ * cd;
            float h_ = o_ * cst;                   // reference omits tanh(c)
            __stcg(&g_h[(size_t)(t + 1) * HH + unit], h_);

            // prefetch gx for next step (overlaps barrier + next dot)
            int tn = (t + 1 < TT) ? (t + 1) : t;
            gxf = __ldcg(&g_gx[0][tn][unit]);
            gxi = __ldcg(&g_gx[1][tn][unit]);
            gxc = __ldcg(&g_gx[2][tn][unit]);
            gxo = __ldcg(&g_gx[3][tn][unit]);
        }

        // ---- grid barrier (round-1 mechanism, fence by thread 0 only) ----
        __syncthreads();
        if (threadIdx.x == 0) {
            __threadfence();                  // release: h store -> counter
            atomicAdd(&g_bar, 1u);
            unsigned tgt = (unsigned)(t + 1) * (unsigned)REC_GRID;
            while (*(volatile unsigned*)&g_bar < tgt) { }
            __threadfence();                  // acquire: counter -> h loads
        }
        __syncthreads();
    }
}

// ---------------------------------------------------------------------------
extern "C" void kernel_launch(void* const* d_in, const int* in_sizes, int n_in,
                              void* d_out, int out_size)
{
    const float* x   = (const float*)d_in[0];
    const float* Wxf = (const float*)d_in[1];
    const float* Whf = (const float*)d_in[2];
    const float* bf  = (const float*)d_in[3];
    const float* Wxi = (const float*)d_in[4];
    const float* Whi = (const float*)d_in[5];
    const float* bi  = (const float*)d_in[6];
    const float* Wxc = (const float*)d_in[7];
    const float* Whc = (const float*)d_in[8];
    const float* bc  = (const float*)d_in[9];
    const float* Wxo = (const float*)d_in[10];
    const float* Who = (const float*)d_in[11];
    const float* bo  = (const float*)d_in[12];
    const float* Wy  = (const float*)d_in[13];
    const float* by  = (const float*)d_in[14];
    float* y = (float*)d_out;

    void* p_gx = nullptr;
    void* p_h  = nullptr;
    cudaGetSymbolAddress(&p_gx, g_gx);
    cudaGetSymbolAddress(&p_h,  g_h);
    float* gx = (float*)p_gx;
    float* hbuf = (float*)p_h;

    init_kernel<<<4, 256>>>();

    // Input projections: 4 GEMMs [4096,1024] = x[4096,512] @ Wx^T + b
    dim3 g1(HH / 64, TT / 64);
    gemm_tn_bias<<<g1, 256>>>(x, Wxf, bf, gx + 0 * (size_t)TT * HH, TT, HH, II);
    gemm_tn_bias<<<g1, 256>>>(x, Wxi, bi, gx + 1 * (size_t)TT * HH, TT, HH, II);
    gemm_tn_bias<<<g1, 256>>>(x, Wxc, bc, gx + 2 * (size_t)TT * HH, TT, HH, II);
    gemm_tn_bias<<<g1, 256>>>(x, Wxo, bo, gx + 3 * (size_t)TT * HH, TT, HH, II);

    // Sequential recurrence (persistent, weights in registers)
    lstm_rec<<<REC_GRID, REC_THREADS>>>(Whf, Whi, Whc, Who);

    // Output projection: y[4096,256] = hs[4096,1024] @ Wy^T + by
    dim3 g2(OO / 64, TT / 64);
    gemm_tn_bias<<<g2, 256>>>(hbuf + HH, Wy, by, y, TT, OO, HH);
}